// round 15
// baseline (speedup 1.0000x reference)
#include <cuda_runtime.h>
#include <cuda_fp16.h>

// Problem: DilatedAttention  q,k,v: [4, 8192, 16, 64] f32 -> out same shape.
// Groups: (g, r, segment, offset, hmin):
//   g0: (6, 1, 2048, 0, 0)   eligible pos: all,       heads 0..5
//   g1: (5, 2, 4096, 1, 5)   eligible pos: p%2==1,    heads 5..9
//   g2: (5, 4, 8192, 2, 10)  eligible pos: p%4==2,    heads 10..14
// head 15 never written (faithful to reference).
//
// History: R8 cp.async lost (barriers serialize warps). R9 last-block
// epilogue lost (threadfence drains stores). R6/R13 reg clamps lost (spills).
// R10 f32x2 speed-neutral (kept: rel_err). R14 WIN: 128-thread blocks
// (narrower barriers, finer tail) pass1 55->50.8. R15: the limit of that
// gradient -- 1-warp blocks: NO barriers, NO smem, register sum
// accumulators, one final half-combine + fire-and-forget double atomics.

#define SEQ   8192
#define BATCH 4
#define HEADS 16
#define DIM   64

#define X0_BASE 0
#define X0_SIZE (BATCH*8192*6*DIM)
#define X1_BASE (X0_BASE + X0_SIZE)
#define X1_SIZE (BATCH*4096*5*DIM)
#define X2_BASE (X1_BASE + X1_SIZE)
#define X2_SIZE (BATCH*2048*5*DIM)
#define X_TOTAL (X2_BASE + X2_SIZE)

#define S0_BASE 0
#define S1_BASE (S0_BASE + BATCH*6*DIM)
#define S2_BASE (S1_BASE + BATCH*5*DIM)
#define S_TOTAL (S2_BASE + BATCH*5*DIM)     // 4096

typedef unsigned long long u64;

__device__ __half  g_xh[X_TOTAL];     // fp16 scratch for x
__device__ double  g_sums[S_TOTAL];   // zero-init; re-zeroed by pass2
__device__ float   g_rsums[S_TOTAL];

// PDL: wait for the preceding kernel's completion before touching memory.
__device__ __forceinline__ void grid_dep_wait() {
    asm volatile("griddepcontrol.wait;" ::: "memory");
}

__global__ void rsums_kernel() {
    grid_dep_wait();   // pass1's g_sums must be complete
    int i = blockIdx.x * blockDim.x + threadIdx.x;
    if (i < S_TOTAL) g_rsums[i] = (float)(1.0 / (3.0 * g_sums[i]));
}

// ---- packed f32x2 helpers (sm_100+ PTX; FFMA2 unreachable from C++) ----
__device__ __forceinline__ u64 mul2(u64 a, u64 b) {
    u64 d; asm("mul.rn.f32x2 %0, %1, %2;" : "=l"(d) : "l"(a), "l"(b)); return d;
}
__device__ __forceinline__ u64 add2(u64 a, u64 b) {
    u64 d; asm("add.rn.f32x2 %0, %1, %2;" : "=l"(d) : "l"(a), "l"(b)); return d;
}
__device__ __forceinline__ u64 fma2(u64 a, u64 b, u64 c) {
    u64 d; asm("fma.rn.f32x2 %0, %1, %2, %3;" : "=l"(d) : "l"(a), "l"(b), "l"(c)); return d;
}
__device__ __forceinline__ float2 u2f(u64 v) {
    float2 f; asm("mov.b64 {%0, %1}, %2;" : "=f"(f.x), "=f"(f.y) : "l"(v)); return f;
}
__device__ __forceinline__ u64 f2u(float x, float y) {
    u64 r; asm("mov.b64 %0, {%1, %2};" : "=l"(r) : "f"(x), "f"(y)); return r;
}
__device__ __forceinline__ float ex2a(float x) {
    float y; asm("ex2.approx.f32 %0, %1;" : "=f"(y) : "f"(x)); return y;
}
__device__ __forceinline__ float rcpa(float x) {
    float y; asm("rcp.approx.f32 %0, %1;" : "=f"(y) : "f"(x)); return y;
}
__device__ __forceinline__ void pref_l2(const void* p) {
    asm volatile("prefetch.global.L2 [%0];" :: "l"(p));
}

// Pass-1 body: ONE WARP per block, 16 eligible positions (8 iterations of
// 2 halves). Lane layout: 16 lanes per position, lane lh owns dims
// [4*lh, 4*lh+4). No smem, no barriers. Q/K/V loaded as ulonglong2 (f32x2
// operands). Q prescaled by 0.125*log2(e) so raw ex2.approx gives
// exp(score/8); no max-subtract (scores ~N(0,1)). Next iteration's rows
// L2-prefetched during current iteration. Sums accumulate in packed f32x2
// registers; one half-combine at the end, then fire-and-forget double
// atomics (REDG, no return wait).
template<int G, int R, int OFF, int HMIN, int PB, int XBASE, int SUMBASE>
__device__ __forceinline__ void pass1_body(
    int blockOffset,
    const float* __restrict__ q,
    const float* __restrict__ k,
    const float* __restrict__ v)
{
    const int lane = threadIdx.x & 31;
    const int half = lane >> 4;
    const int lh   = lane & 15;

    const int blockBase = blockOffset * 16;   // eligible-position index (global)
    const int b = blockBase / PB;             // 16 divides PB; no batch straddle

    const u64 C2 = f2u(0.18033688f, 0.18033688f);   // 0.125 * log2(e)

    // Register sum accumulators: per (head, this lane's 4 dims).
    u64 accLo[G], accHi[G];
    #pragma unroll
    for (int a = 0; a < G; a++) { accLo[a] = 0ull; accHi[a] = 0ull; }

    // rowbase advance per iteration: +2 eligible positions.
    constexpr int ROWSTEP = 2 * R * HEADS * DIM;

    #pragma unroll 1
    for (int it = 0; it < 8; it++) {
        const int j  = blockBase + it * 2 + half;   // global eligible idx
        const int jb = j - b * PB;
        const int p  = jb * R + OFF;
        const int rowbase = (((b * SEQ + p) * HEADS + HMIN) * DIM) + 4 * lh;

        // Q heads resident as prescaled f32x2 pairs; K streamed per head.
        u64 qlo[G], qhi[G];
        #pragma unroll
        for (int a = 0; a < G; a++) {
            const ulonglong2 t = *reinterpret_cast<const ulonglong2*>(q + rowbase + a * DIM);
            qlo[a] = mul2(t.x, C2);
            qhi[a] = mul2(t.y, C2);
        }

        float s[G][G];   // scaled score partials (this lane's 4 dims)
        #pragma unroll
        for (int c = 0; c < G; c++) {
            const ulonglong2 kc = *reinterpret_cast<const ulonglong2*>(k + rowbase + c * DIM);
            #pragma unroll
            for (int a = 0; a < G; a++) {
                const u64 acc = fma2(qhi[a], kc.y, mul2(qlo[a], kc.x));
                const float2 f = u2f(acc);
                s[a][c] = f.x + f.y;
            }
        }

        // Hoist V loads (qlo/qhi dead; loads covered by shuffles + softmax).
        ulonglong2 vv[G];
        #pragma unroll
        for (int c = 0; c < G; c++)
            vv[c] = *reinterpret_cast<const ulonglong2*>(v + rowbase + c * DIM);

        // L2-prefetch next iteration's rows (overlaps butterfly/softmax/AV).
        if (it < 7) {
            const int nb = rowbase + ROWSTEP;
            #pragma unroll
            for (int a = 0; a < G; a++) {
                pref_l2(q + nb + a * DIM);
                pref_l2(k + nb + a * DIM);
                pref_l2(v + nb + a * DIM);
            }
        }

        // Butterfly reduce within each 16-lane half (scalar: keeps regs flat).
        #pragma unroll
        for (int m = 1; m < 16; m <<= 1)
            #pragma unroll
            for (int a = 0; a < G; a++)
                #pragma unroll
                for (int c = 0; c < G; c++)
                    s[a][c] += __shfl_xor_sync(0xffffffffu, s[a][c], m);

        // Per row: w = 2^s, rinv = 1/sum(w); AV via packed FFMA2, rinv
        // folded into the final xo scale; sums into register accumulators.
        const int xbase = XBASE + (j * G) * DIM + 4 * lh;
        #pragma unroll
        for (int a = 0; a < G; a++) {
            float tot = 0.0f;
            #pragma unroll
            for (int c = 0; c < G; c++) {
                s[a][c] = ex2a(s[a][c]);
                tot += s[a][c];
            }
            const float rinv = rcpa(tot);

            u64 xlo = 0ull, xhi = 0ull;   // (+0.0f, +0.0f)
            #pragma unroll
            for (int c = 0; c < G; c++) {
                const u64 w2 = f2u(s[a][c], s[a][c]);
                xlo = fma2(w2, vv[c].x, xlo);
                xhi = fma2(w2, vv[c].y, xhi);
            }
            const u64 r2 = f2u(rinv, rinv);
            xlo = mul2(xlo, r2);
            xhi = mul2(xhi, r2);

            // fp16 store of this head's 4 dims.
            const float2 f01 = u2f(xlo);
            const float2 f23 = u2f(xhi);
            const __half2 h01 = __floats2half2_rn(f01.x, f01.y);
            const __half2 h23 = __floats2half2_rn(f23.x, f23.y);
            uint2 raw;
            raw.x = *reinterpret_cast<const unsigned int*>(&h01);
            raw.y = *reinterpret_cast<const unsigned int*>(&h23);
            *reinterpret_cast<uint2*>(g_xh + xbase + a * DIM) = raw;

            // Accumulate sums in registers (no per-iter combine/smem).
            accLo[a] = add2(accLo[a], xlo);
            accHi[a] = add2(accHi[a], xhi);
        }
    }

    // Final: combine the two halves once, then double atomics (no return ->
    // REDG fire-and-forget; 4096 L2-hot addresses, fully overlapped).
    #pragma unroll
    for (int a = 0; a < G; a++) {
        accLo[a] = add2(accLo[a], __shfl_down_sync(0xffffffffu, accLo[a], 16));
        accHi[a] = add2(accHi[a], __shfl_down_sync(0xffffffffu, accHi[a], 16));
    }
    if (half == 0) {
        double* base = g_sums + SUMBASE + b * (G * 64) + 4 * lh;
        #pragma unroll
        for (int a = 0; a < G; a++) {
            const float2 f01 = u2f(accLo[a]);
            const float2 f23 = u2f(accHi[a]);
            atomicAdd(base + a * 64 + 0, (double)f01.x);
            atomicAdd(base + a * 64 + 1, (double)f01.y);
            atomicAdd(base + a * 64 + 2, (double)f23.x);
            atomicAdd(base + a * 64 + 3, (double)f23.y);
        }
    }
}

// Fused pass 1 (32 threads/block = 1 warp, 16 positions/block):
// blocks [0,2048): g0, [2048,3072): g1, [3072,3584): g2.
__global__ void __launch_bounds__(32) pass1_fused_kernel(
    const float* __restrict__ q,
    const float* __restrict__ k,
    const float* __restrict__ v)
{
    grid_dep_wait();   // PDL: gate before any memory op
    const int bx = blockIdx.x;
    if (bx < 2048) {
        pass1_body<6, 1, 0, 0, 8192, X0_BASE, S0_BASE>(bx, q, k, v);
    } else if (bx < 3072) {
        pass1_body<5, 2, 1, 5, 4096, X1_BASE, S1_BASE>(bx - 2048, q, k, v);
    } else {
        pass1_body<5, 4, 2, 10, 2048, X2_BASE, S2_BASE>(bx - 3072, q, k, v);
    }
}

__device__ __forceinline__ float4 xload(int xoff, float4 rv)
{
    const uint2 raw = *reinterpret_cast<const uint2*>(g_xh + xoff);
    const __half2 h01 = *reinterpret_cast<const __half2*>(&raw.x);
    const __half2 h23 = *reinterpret_cast<const __half2*>(&raw.y);
    const float2 f01 = __half22float2(h01);
    const float2 f23 = __half22float2(h23);
    return make_float4(f01.x * rv.x, f01.y * rv.y, f23.x * rv.z, f23.y * rv.w);
}

// Pass 2: each thread writes EIGHT float4s at positions ph + i*1024, i=0..7
// (stride 1024 preserves parity -> identical group predicates, shared rsums,
// 8-deep load MLP). t layout: d4 (16) | h (16) | ph (1024) | b (4).
// Also re-zeroes g_sums (already consumed by rsums_kernel) for next launch.
__global__ void __launch_bounds__(256) pass2_kernel(float* __restrict__ out)
{
    grid_dep_wait();   // rsums_kernel must have finished reading g_sums

    const int t = blockIdx.x * 256 + threadIdx.x;
    if (t < S_TOTAL) g_sums[t] = 0.0;

    const int d4 = t & 15;
    const int h  = (t >> 4) & 15;
    const int ph = (t >> 8) & 1023;     // p_i = ph + i*1024, i in 0..7
    const int b  = t >> 18;

    float4 vo[8];
    #pragma unroll
    for (int i = 0; i < 8; i++) vo[i] = make_float4(0.f, 0.f, 0.f, 0.f);

    const int e = (d4 << 2);

    if (h < 6) { // group 0: all positions
        const float4 rv = *reinterpret_cast<const float4*>(
            g_rsums + S0_BASE + (((b * 6 + h) << 6) + e));
        const int j0 = b * 8192 + ph;           // j stride per output = 1024
        #pragma unroll
        for (int i = 0; i < 8; i++)
            vo[i] = xload(X0_BASE + (((j0 + i * 1024) * 6 + h) << 6) + e, rv);
    }
    if (h >= 5 && h < 10 && (ph & 1) == 1) { // group 1: odd positions
        const int hh = h - 5;
        const float4 rv = *reinterpret_cast<const float4*>(
            g_rsums + S1_BASE + (((b * 5 + hh) << 6) + e));
        const int j0 = b * 4096 + (ph >> 1);    // j stride per output = 512
        #pragma unroll
        for (int i = 0; i < 8; i++) {
            const float4 ti = xload(X1_BASE + (((j0 + i * 512) * 5 + hh) << 6) + e, rv);
            vo[i].x += ti.x; vo[i].y += ti.y; vo[i].z += ti.z; vo[i].w += ti.w;
        }
    }
    if (h >= 10 && h < 15 && (ph & 3) == 2) { // group 2: pos%4==2
        const int hh = h - 10;
        const float4 rv = *reinterpret_cast<const float4*>(
            g_rsums + S2_BASE + (((b * 5 + hh) << 6) + e));
        const int j0 = b * 2048 + (ph >> 2);    // j stride per output = 256
        #pragma unroll
        for (int i = 0; i < 8; i++) {
            const float4 ti = xload(X2_BASE + (((j0 + i * 256) * 5 + hh) << 6) + e, rv);
            vo[i].x += ti.x; vo[i].y += ti.y; vo[i].z += ti.z; vo[i].w += ti.w;
        }
    }

    const int o0 = (b * 8192 + ph) * 256 + h * 16 + d4;  // float4 index
    const int ostride = 1024 * 256;
    float4* o = reinterpret_cast<float4*>(out);
    #pragma unroll
    for (int i = 0; i < 8; i++)
        o[o0 + i * ostride] = vo[i];
}

// Launch with Programmatic Stream Serialization: launch latency overlaps the
// preceding kernel's tail; ordering enforced by griddepcontrol.wait inside.
template <typename... Args>
static inline void launch_pdl(void (*fn)(Args...), dim3 grid, dim3 block,
                              Args... args)
{
    cudaLaunchConfig_t cfg = {};
    cfg.gridDim  = grid;
    cfg.blockDim = block;
    cfg.dynamicSmemBytes = 0;
    cfg.stream   = 0;
    cudaLaunchAttribute attr[1];
    attr[0].id = cudaLaunchAttributeProgrammaticStreamSerialization;
    attr[0].val.programmaticStreamSerializationAllowed = 1;
    cfg.attrs    = attr;
    cfg.numAttrs = 1;
    cudaLaunchKernelEx(&cfg, fn, args...);
}

extern "C" void kernel_launch(void* const* d_in, const int* in_sizes, int n_in,
                              void* d_out, int out_size)
{
    const float* q = (const float*)d_in[0];
    const float* k = (const float*)d_in[1];
    const float* v = (const float*)d_in[2];
    float* out = (float*)d_out;

    // Pass 1: 2048 (g0) + 1024 (g1) + 512 (g2) one-warp blocks, 16 pos each.
    // g_sums starts zeroed (static init; re-zeroed by pass2 each launch).
    launch_pdl(pass1_fused_kernel, dim3(3584), dim3(32), q, k, v);

    // rsums + pass2 ride PDL.
    launch_pdl(rsums_kernel, dim3(16), dim3(256));
    launch_pdl(pass2_kernel, dim3(4096), dim3(256), out);
}

// round 16
// speedup vs baseline: 1.2747x; 1.2747x over previous
#include <cuda_runtime.h>
#include <cuda_fp16.h>

// Problem: DilatedAttention  q,k,v: [4, 8192, 16, 64] f32 -> out same shape.
// Groups: (g, r, segment, offset, hmin):
//   g0: (6, 1, 2048, 0, 0)   eligible pos: all,       heads 0..5
//   g1: (5, 2, 4096, 1, 5)   eligible pos: p%2==1,    heads 5..9
//   g2: (5, 4, 8192, 2, 10)  eligible pos: p%4==2,    heads 10..14
// head 15 never written (faithful to reference).
//
// History: R8 cp.async lost (barriers serialize warps). R9 last-block
// epilogue lost (threadfence drains stores). R6/R13 reg clamps lost (spills).
// R15 1-warp blocks + reg accumulators lost (regs 127, occ collapse).
// R10 f32x2 speed-neutral (kept: rel_err). R14 WIN: 128-thread blocks,
// pass1 55->50.8. R16: isolate the block-size gradient -- R14 body
// unchanged, 64-thread blocks (2 warps, 16 pos, smem sums preserved).

#define SEQ   8192
#define BATCH 4
#define HEADS 16
#define DIM   64

#define X0_BASE 0
#define X0_SIZE (BATCH*8192*6*DIM)
#define X1_BASE (X0_BASE + X0_SIZE)
#define X1_SIZE (BATCH*4096*5*DIM)
#define X2_BASE (X1_BASE + X1_SIZE)
#define X2_SIZE (BATCH*2048*5*DIM)
#define X_TOTAL (X2_BASE + X2_SIZE)

#define S0_BASE 0
#define S1_BASE (S0_BASE + BATCH*6*DIM)
#define S2_BASE (S1_BASE + BATCH*5*DIM)
#define S_TOTAL (S2_BASE + BATCH*5*DIM)     // 4096

typedef unsigned long long u64;

__device__ __half  g_xh[X_TOTAL];     // fp16 scratch for x
__device__ double  g_sums[S_TOTAL];   // zero-init; re-zeroed by pass2
__device__ float   g_rsums[S_TOTAL];

// PDL: wait for the preceding kernel's completion before touching memory.
__device__ __forceinline__ void grid_dep_wait() {
    asm volatile("griddepcontrol.wait;" ::: "memory");
}

__global__ void rsums_kernel() {
    grid_dep_wait();   // pass1's g_sums must be complete
    int i = blockIdx.x * blockDim.x + threadIdx.x;
    if (i < S_TOTAL) g_rsums[i] = (float)(1.0 / (3.0 * g_sums[i]));
}

// ---- packed f32x2 helpers (sm_100+ PTX; FFMA2 unreachable from C++) ----
__device__ __forceinline__ u64 mul2(u64 a, u64 b) {
    u64 d; asm("mul.rn.f32x2 %0, %1, %2;" : "=l"(d) : "l"(a), "l"(b)); return d;
}
__device__ __forceinline__ u64 add2(u64 a, u64 b) {
    u64 d; asm("add.rn.f32x2 %0, %1, %2;" : "=l"(d) : "l"(a), "l"(b)); return d;
}
__device__ __forceinline__ u64 fma2(u64 a, u64 b, u64 c) {
    u64 d; asm("fma.rn.f32x2 %0, %1, %2, %3;" : "=l"(d) : "l"(a), "l"(b), "l"(c)); return d;
}
__device__ __forceinline__ float2 u2f(u64 v) {
    float2 f; asm("mov.b64 {%0, %1}, %2;" : "=f"(f.x), "=f"(f.y) : "l"(v)); return f;
}
__device__ __forceinline__ u64 f2u(float x, float y) {
    u64 r; asm("mov.b64 %0, {%1, %2};" : "=l"(r) : "f"(x), "f"(y)); return r;
}
__device__ __forceinline__ float ex2a(float x) {
    float y; asm("ex2.approx.f32 %0, %1;" : "=f"(y) : "f"(x)); return y;
}
__device__ __forceinline__ float rcpa(float x) {
    float y; asm("rcp.approx.f32 %0, %1;" : "=f"(y) : "f"(x)); return y;
}
__device__ __forceinline__ void pref_l2(const void* p) {
    asm volatile("prefetch.global.L2 [%0];" :: "l"(p));
}

// Pass-1 body: one block = 16 eligible positions (4 iterations of
// 2 warps x 2 halves, 64 threads). Lane layout: 16 lanes per position,
// lane lh owns dims [4*lh, 4*lh+4). Q/K/V loaded as ulonglong2 (f32x2
// operands). Q prescaled by 0.125*log2(e) so raw ex2.approx gives
// exp(score/8); no max-subtract (scores ~N(0,1)). Next iteration's rows
// L2-prefetched during current iteration. Sums: per-warp private smem
// slice, block-reduced once in double -> one double atomic per element.
template<int G, int R, int OFF, int HMIN, int PB, int XBASE, int SUMBASE>
__device__ __forceinline__ void pass1_body(
    int blockOffset, float* sblk,   // 2 slices of G*64 floats
    const float* __restrict__ q,
    const float* __restrict__ k,
    const float* __restrict__ v)
{
    const int tid  = threadIdx.x;
    const int w    = tid >> 5;     // 0..1
    const int lane = tid & 31;
    const int half = lane >> 4;
    const int lh   = lane & 15;

    for (int i = tid; i < 2 * G * 64; i += 64) sblk[i] = 0.0f;
    __syncthreads();

    float* myslice = sblk + w * (G * 64);

    const int blockBase = blockOffset * 16;   // eligible-position index (global)
    const int b = blockBase / PB;             // 16 divides PB; no batch straddle

    const u64 C2 = f2u(0.18033688f, 0.18033688f);   // 0.125 * log2(e)

    // rowbase advance per iteration: +4 eligible positions.
    constexpr int ROWSTEP = 4 * R * HEADS * DIM;

    #pragma unroll 1
    for (int it = 0; it < 4; it++) {
        const int j  = blockBase + it * 4 + w * 2 + half;  // global eligible idx
        const int jb = j - b * PB;
        const int p  = jb * R + OFF;
        const int rowbase = (((b * SEQ + p) * HEADS + HMIN) * DIM) + 4 * lh;

        // Q heads resident as prescaled f32x2 pairs; K streamed per head.
        u64 qlo[G], qhi[G];
        #pragma unroll
        for (int a = 0; a < G; a++) {
            const ulonglong2 t = *reinterpret_cast<const ulonglong2*>(q + rowbase + a * DIM);
            qlo[a] = mul2(t.x, C2);
            qhi[a] = mul2(t.y, C2);
        }

        float s[G][G];   // scaled score partials (this lane's 4 dims)
        #pragma unroll
        for (int c = 0; c < G; c++) {
            const ulonglong2 kc = *reinterpret_cast<const ulonglong2*>(k + rowbase + c * DIM);
            #pragma unroll
            for (int a = 0; a < G; a++) {
                const u64 acc = fma2(qhi[a], kc.y, mul2(qlo[a], kc.x));
                const float2 f = u2f(acc);
                s[a][c] = f.x + f.y;
            }
        }

        // Hoist V loads (qlo/qhi dead; loads covered by shuffles + softmax).
        ulonglong2 vv[G];
        #pragma unroll
        for (int c = 0; c < G; c++)
            vv[c] = *reinterpret_cast<const ulonglong2*>(v + rowbase + c * DIM);

        // L2-prefetch next iteration's rows (overlaps butterfly/softmax/AV).
        if (it < 3) {
            const int nb = rowbase + ROWSTEP;
            #pragma unroll
            for (int a = 0; a < G; a++) {
                pref_l2(q + nb + a * DIM);
                pref_l2(k + nb + a * DIM);
                pref_l2(v + nb + a * DIM);
            }
        }

        // Butterfly reduce within each 16-lane half (scalar: keeps regs flat).
        #pragma unroll
        for (int m = 1; m < 16; m <<= 1)
            #pragma unroll
            for (int a = 0; a < G; a++)
                #pragma unroll
                for (int c = 0; c < G; c++)
                    s[a][c] += __shfl_xor_sync(0xffffffffu, s[a][c], m);

        // Per row: w = 2^s, rinv = 1/sum(w); AV via packed FFMA2, rinv
        // folded into the final xo scale.
        const int xbase = XBASE + (j * G) * DIM + 4 * lh;
        #pragma unroll
        for (int a = 0; a < G; a++) {
            float tot = 0.0f;
            #pragma unroll
            for (int c = 0; c < G; c++) {
                s[a][c] = ex2a(s[a][c]);
                tot += s[a][c];
            }
            const float rinv = rcpa(tot);

            u64 xlo = 0ull, xhi = 0ull;   // (+0.0f, +0.0f)
            #pragma unroll
            for (int c = 0; c < G; c++) {
                const u64 w2 = f2u(s[a][c], s[a][c]);
                xlo = fma2(w2, vv[c].x, xlo);
                xhi = fma2(w2, vv[c].y, xhi);
            }
            const u64 r2 = f2u(rinv, rinv);
            xlo = mul2(xlo, r2);
            xhi = mul2(xhi, r2);

            // fp16 store of this head's 4 dims.
            const float2 f01 = u2f(xlo);
            const float2 f23 = u2f(xhi);
            const __half2 h01 = __floats2half2_rn(f01.x, f01.y);
            const __half2 h23 = __floats2half2_rn(f23.x, f23.y);
            uint2 raw;
            raw.x = *reinterpret_cast<const unsigned int*>(&h01);
            raw.y = *reinterpret_cast<const unsigned int*>(&h23);
            *reinterpret_cast<uint2*>(g_xh + xbase + a * DIM) = raw;

            // Combine halves on packed values, add into this warp's slice
            // (half==0 lanes write distinct float4 slots -- race-free).
            const u64 olo = __shfl_down_sync(0xffffffffu, xlo, 16);
            const u64 ohi = __shfl_down_sync(0xffffffffu, xhi, 16);
            xlo = add2(xlo, olo);
            xhi = add2(xhi, ohi);
            if (half == 0) {
                const float2 a01 = u2f(xlo);
                const float2 a23 = u2f(xhi);
                float4* slot = reinterpret_cast<float4*>(myslice + a * 64 + 4 * lh);
                float4 cur = *slot;
                cur.x += a01.x; cur.y += a01.y;
                cur.z += a23.x; cur.w += a23.y;
                *slot = cur;
            }
        }
    }

    __syncthreads();
    // Reduce the 2 warp slices in double, one global double atomic per element.
    for (int i = tid; i < G * 64; i += 64) {
        double tot = (double)sblk[i] + (double)sblk[G * 64 + i];
        atomicAdd(&g_sums[SUMBASE + b * (G * 64) + i], tot);
    }
}

// Fused pass 1 (64 threads/block = 2 warps, 16 positions/block):
// blocks [0,2048): g0, [2048,3072): g1, [3072,3584): g2.
__global__ void __launch_bounds__(64) pass1_fused_kernel(
    const float* __restrict__ q,
    const float* __restrict__ k,
    const float* __restrict__ v)
{
    grid_dep_wait();   // PDL: gate before any memory op
    __shared__ float sblk[2 * 6 * 64];   // 3 KB: per-warp sum slices
    const int bx = blockIdx.x;
    if (bx < 2048) {
        pass1_body<6, 1, 0, 0, 8192, X0_BASE, S0_BASE>(bx, sblk, q, k, v);
    } else if (bx < 3072) {
        pass1_body<5, 2, 1, 5, 4096, X1_BASE, S1_BASE>(bx - 2048, sblk, q, k, v);
    } else {
        pass1_body<5, 4, 2, 10, 2048, X2_BASE, S2_BASE>(bx - 3072, sblk, q, k, v);
    }
}

__device__ __forceinline__ float4 xload(int xoff, float4 rv)
{
    const uint2 raw = *reinterpret_cast<const uint2*>(g_xh + xoff);
    const __half2 h01 = *reinterpret_cast<const __half2*>(&raw.x);
    const __half2 h23 = *reinterpret_cast<const __half2*>(&raw.y);
    const float2 f01 = __half22float2(h01);
    const float2 f23 = __half22float2(h23);
    return make_float4(f01.x * rv.x, f01.y * rv.y, f23.x * rv.z, f23.y * rv.w);
}

// Pass 2: each thread writes EIGHT float4s at positions ph + i*1024, i=0..7
// (stride 1024 preserves parity -> identical group predicates, shared rsums,
// 8-deep load MLP). t layout: d4 (16) | h (16) | ph (1024) | b (4).
// Also re-zeroes g_sums (already consumed by rsums_kernel) for next launch.
__global__ void __launch_bounds__(256) pass2_kernel(float* __restrict__ out)
{
    grid_dep_wait();   // rsums_kernel must have finished reading g_sums

    const int t = blockIdx.x * 256 + threadIdx.x;
    if (t < S_TOTAL) g_sums[t] = 0.0;

    const int d4 = t & 15;
    const int h  = (t >> 4) & 15;
    const int ph = (t >> 8) & 1023;     // p_i = ph + i*1024, i in 0..7
    const int b  = t >> 18;

    float4 vo[8];
    #pragma unroll
    for (int i = 0; i < 8; i++) vo[i] = make_float4(0.f, 0.f, 0.f, 0.f);

    const int e = (d4 << 2);

    if (h < 6) { // group 0: all positions
        const float4 rv = *reinterpret_cast<const float4*>(
            g_rsums + S0_BASE + (((b * 6 + h) << 6) + e));
        const int j0 = b * 8192 + ph;           // j stride per output = 1024
        #pragma unroll
        for (int i = 0; i < 8; i++)
            vo[i] = xload(X0_BASE + (((j0 + i * 1024) * 6 + h) << 6) + e, rv);
    }
    if (h >= 5 && h < 10 && (ph & 1) == 1) { // group 1: odd positions
        const int hh = h - 5;
        const float4 rv = *reinterpret_cast<const float4*>(
            g_rsums + S1_BASE + (((b * 5 + hh) << 6) + e));
        const int j0 = b * 4096 + (ph >> 1);    // j stride per output = 512
        #pragma unroll
        for (int i = 0; i < 8; i++) {
            const float4 ti = xload(X1_BASE + (((j0 + i * 512) * 5 + hh) << 6) + e, rv);
            vo[i].x += ti.x; vo[i].y += ti.y; vo[i].z += ti.z; vo[i].w += ti.w;
        }
    }
    if (h >= 10 && h < 15 && (ph & 3) == 2) { // group 2: pos%4==2
        const int hh = h - 10;
        const float4 rv = *reinterpret_cast<const float4*>(
            g_rsums + S2_BASE + (((b * 5 + hh) << 6) + e));
        const int j0 = b * 2048 + (ph >> 2);    // j stride per output = 256
        #pragma unroll
        for (int i = 0; i < 8; i++) {
            const float4 ti = xload(X2_BASE + (((j0 + i * 256) * 5 + hh) << 6) + e, rv);
            vo[i].x += ti.x; vo[i].y += ti.y; vo[i].z += ti.z; vo[i].w += ti.w;
        }
    }

    const int o0 = (b * 8192 + ph) * 256 + h * 16 + d4;  // float4 index
    const int ostride = 1024 * 256;
    float4* o = reinterpret_cast<float4*>(out);
    #pragma unroll
    for (int i = 0; i < 8; i++)
        o[o0 + i * ostride] = vo[i];
}

// Launch with Programmatic Stream Serialization: launch latency overlaps the
// preceding kernel's tail; ordering enforced by griddepcontrol.wait inside.
template <typename... Args>
static inline void launch_pdl(void (*fn)(Args...), dim3 grid, dim3 block,
                              Args... args)
{
    cudaLaunchConfig_t cfg = {};
    cfg.gridDim  = grid;
    cfg.blockDim = block;
    cfg.dynamicSmemBytes = 0;
    cfg.stream   = 0;
    cudaLaunchAttribute attr[1];
    attr[0].id = cudaLaunchAttributeProgrammaticStreamSerialization;
    attr[0].val.programmaticStreamSerializationAllowed = 1;
    cfg.attrs    = attr;
    cfg.numAttrs = 1;
    cudaLaunchKernelEx(&cfg, fn, args...);
}

extern "C" void kernel_launch(void* const* d_in, const int* in_sizes, int n_in,
                              void* d_out, int out_size)
{
    const float* q = (const float*)d_in[0];
    const float* k = (const float*)d_in[1];
    const float* v = (const float*)d_in[2];
    float* out = (float*)d_out;

    // Pass 1: 2048 (g0) + 1024 (g1) + 512 (g2) two-warp blocks, 16 pos each.
    // g_sums starts zeroed (static init; re-zeroed by pass2 each launch).
    launch_pdl(pass1_fused_kernel, dim3(3584), dim3(64), q, k, v);

    // rsums + pass2 ride PDL.
    launch_pdl(rsums_kernel, dim3(16), dim3(256));
    launch_pdl(pass2_kernel, dim3(4096), dim3(256), out);
}

// round 17
// speedup vs baseline: 1.3151x; 1.0317x over previous
#include <cuda_runtime.h>
#include <cuda_fp16.h>

// Problem: DilatedAttention  q,k,v: [4, 8192, 16, 64] f32 -> out same shape.
// Groups: (g, r, segment, offset, hmin):
//   g0: (6, 1, 2048, 0, 0)   eligible pos: all,       heads 0..5
//   g1: (5, 2, 4096, 1, 5)   eligible pos: p%2==1,    heads 5..9
//   g2: (5, 4, 8192, 2, 10)  eligible pos: p%4==2,    heads 10..14
// head 15 never written (faithful to reference).
//
// History: R8 cp.async lost (barriers). R9 epilogue lost (threadfence).
// R6/R13 reg clamps lost (spills). R15 1-warp lost (regs 127). R16 64-thr
// lost (per-block overhead). Block-size curve: 256->55.0, 128->50.8 BEST,
// 64->56.9, 32->78. R14 = anchor (85.9). R17: R14 + evict-first loads for
// streamed Q/K/V (__ldcs), streaming output stores (__stcs) so fp16 x stays
// L2-resident for pass2, + heavier g0 blocks scheduled first (LPT tail).

#define SEQ   8192
#define BATCH 4
#define HEADS 16
#define DIM   64

#define X0_BASE 0
#define X0_SIZE (BATCH*8192*6*DIM)
#define X1_BASE (X0_BASE + X0_SIZE)
#define X1_SIZE (BATCH*4096*5*DIM)
#define X2_BASE (X1_BASE + X1_SIZE)
#define X2_SIZE (BATCH*2048*5*DIM)
#define X_TOTAL (X2_BASE + X2_SIZE)

#define S0_BASE 0
#define S1_BASE (S0_BASE + BATCH*6*DIM)
#define S2_BASE (S1_BASE + BATCH*5*DIM)
#define S_TOTAL (S2_BASE + BATCH*5*DIM)     // 4096

typedef unsigned long long u64;

__device__ __half  g_xh[X_TOTAL];     // fp16 scratch for x
__device__ double  g_sums[S_TOTAL];   // zero-init; re-zeroed by pass2
__device__ float   g_rsums[S_TOTAL];

// PDL: wait for the preceding kernel's completion before touching memory.
__device__ __forceinline__ void grid_dep_wait() {
    asm volatile("griddepcontrol.wait;" ::: "memory");
}

__global__ void rsums_kernel() {
    grid_dep_wait();   // pass1's g_sums must be complete
    int i = blockIdx.x * blockDim.x + threadIdx.x;
    if (i < S_TOTAL) g_rsums[i] = (float)(1.0 / (3.0 * g_sums[i]));
}

// ---- packed f32x2 helpers (sm_100+ PTX; FFMA2 unreachable from C++) ----
__device__ __forceinline__ u64 mul2(u64 a, u64 b) {
    u64 d; asm("mul.rn.f32x2 %0, %1, %2;" : "=l"(d) : "l"(a), "l"(b)); return d;
}
__device__ __forceinline__ u64 add2(u64 a, u64 b) {
    u64 d; asm("add.rn.f32x2 %0, %1, %2;" : "=l"(d) : "l"(a), "l"(b)); return d;
}
__device__ __forceinline__ u64 fma2(u64 a, u64 b, u64 c) {
    u64 d; asm("fma.rn.f32x2 %0, %1, %2, %3;" : "=l"(d) : "l"(a), "l"(b), "l"(c)); return d;
}
__device__ __forceinline__ float2 u2f(u64 v) {
    float2 f; asm("mov.b64 {%0, %1}, %2;" : "=f"(f.x), "=f"(f.y) : "l"(v)); return f;
}
__device__ __forceinline__ u64 f2u(float x, float y) {
    u64 r; asm("mov.b64 %0, {%1, %2};" : "=l"(r) : "f"(x), "f"(y)); return r;
}
__device__ __forceinline__ float ex2a(float x) {
    float y; asm("ex2.approx.f32 %0, %1;" : "=f"(y) : "f"(x)); return y;
}
__device__ __forceinline__ float rcpa(float x) {
    float y; asm("rcp.approx.f32 %0, %1;" : "=f"(y) : "f"(x)); return y;
}
__device__ __forceinline__ void pref_l2(const void* p) {
    asm volatile("prefetch.global.L2 [%0];" :: "l"(p));
}
// Evict-first 16B load (streamed Q/K/V: never re-read -> don't pollute L2).
__device__ __forceinline__ ulonglong2 ldcs2(const float* p) {
    ulonglong2 r;
    asm("ld.global.cs.v2.u64 {%0, %1}, [%2];"
        : "=l"(r.x), "=l"(r.y) : "l"(p));
    return r;
}

// Pass-1 body: one block = 32 eligible positions (4 iterations of
// 4 warps x 2 halves, 128 threads). Lane layout: 16 lanes per position,
// lane lh owns dims [4*lh, 4*lh+4). Q/K/V loaded evict-first as ulonglong2
// (f32x2 operands). Q prescaled by 0.125*log2(e) so raw ex2.approx gives
// exp(score/8); no max-subtract (scores ~N(0,1)). Next iteration's rows
// L2-prefetched during current iteration. Sums: per-warp private smem
// slice, block-reduced once in double -> one double atomic per element.
template<int G, int R, int OFF, int HMIN, int PB, int XBASE, int SUMBASE>
__device__ __forceinline__ void pass1_body(
    int blockOffset, float* sblk,   // 4 slices of G*64 floats
    const float* __restrict__ q,
    const float* __restrict__ k,
    const float* __restrict__ v)
{
    const int tid  = threadIdx.x;
    const int w    = tid >> 5;     // 0..3
    const int lane = tid & 31;
    const int half = lane >> 4;
    const int lh   = lane & 15;

    for (int i = tid; i < 4 * G * 64; i += 128) sblk[i] = 0.0f;
    __syncthreads();

    float* myslice = sblk + w * (G * 64);

    const int blockBase = blockOffset * 32;   // eligible-position index (global)
    const int b = blockBase / PB;             // 32 divides PB; no batch straddle

    const u64 C2 = f2u(0.18033688f, 0.18033688f);   // 0.125 * log2(e)

    // rowbase advance per iteration: +8 eligible positions.
    constexpr int ROWSTEP = 8 * R * HEADS * DIM;

    #pragma unroll 1
    for (int it = 0; it < 4; it++) {
        const int j  = blockBase + it * 8 + w * 2 + half;  // global eligible idx
        const int jb = j - b * PB;
        const int p  = jb * R + OFF;
        const int rowbase = (((b * SEQ + p) * HEADS + HMIN) * DIM) + 4 * lh;

        // Q heads resident as prescaled f32x2 pairs; K streamed per head.
        u64 qlo[G], qhi[G];
        #pragma unroll
        for (int a = 0; a < G; a++) {
            const ulonglong2 t = ldcs2(q + rowbase + a * DIM);
            qlo[a] = mul2(t.x, C2);
            qhi[a] = mul2(t.y, C2);
        }

        float s[G][G];   // scaled score partials (this lane's 4 dims)
        #pragma unroll
        for (int c = 0; c < G; c++) {
            const ulonglong2 kc = ldcs2(k + rowbase + c * DIM);
            #pragma unroll
            for (int a = 0; a < G; a++) {
                const u64 acc = fma2(qhi[a], kc.y, mul2(qlo[a], kc.x));
                const float2 f = u2f(acc);
                s[a][c] = f.x + f.y;
            }
        }

        // Hoist V loads (qlo/qhi dead; loads covered by shuffles + softmax).
        ulonglong2 vv[G];
        #pragma unroll
        for (int c = 0; c < G; c++)
            vv[c] = ldcs2(v + rowbase + c * DIM);

        // L2-prefetch next iteration's rows (overlaps butterfly/softmax/AV).
        if (it < 3) {
            const int nb = rowbase + ROWSTEP;
            #pragma unroll
            for (int a = 0; a < G; a++) {
                pref_l2(q + nb + a * DIM);
                pref_l2(k + nb + a * DIM);
                pref_l2(v + nb + a * DIM);
            }
        }

        // Butterfly reduce within each 16-lane half (scalar: keeps regs flat).
        #pragma unroll
        for (int m = 1; m < 16; m <<= 1)
            #pragma unroll
            for (int a = 0; a < G; a++)
                #pragma unroll
                for (int c = 0; c < G; c++)
                    s[a][c] += __shfl_xor_sync(0xffffffffu, s[a][c], m);

        // Per row: w = 2^s, rinv = 1/sum(w); AV via packed FFMA2, rinv
        // folded into the final xo scale.
        const int xbase = XBASE + (j * G) * DIM + 4 * lh;
        #pragma unroll
        for (int a = 0; a < G; a++) {
            float tot = 0.0f;
            #pragma unroll
            for (int c = 0; c < G; c++) {
                s[a][c] = ex2a(s[a][c]);
                tot += s[a][c];
            }
            const float rinv = rcpa(tot);

            u64 xlo = 0ull, xhi = 0ull;   // (+0.0f, +0.0f)
            #pragma unroll
            for (int c = 0; c < G; c++) {
                const u64 w2 = f2u(s[a][c], s[a][c]);
                xlo = fma2(w2, vv[c].x, xlo);
                xhi = fma2(w2, vv[c].y, xhi);
            }
            const u64 r2 = f2u(rinv, rinv);
            xlo = mul2(xlo, r2);
            xhi = mul2(xhi, r2);

            // fp16 store of this head's 4 dims (default policy: pass2 reads it).
            const float2 f01 = u2f(xlo);
            const float2 f23 = u2f(xhi);
            const __half2 h01 = __floats2half2_rn(f01.x, f01.y);
            const __half2 h23 = __floats2half2_rn(f23.x, f23.y);
            uint2 raw;
            raw.x = *reinterpret_cast<const unsigned int*>(&h01);
            raw.y = *reinterpret_cast<const unsigned int*>(&h23);
            *reinterpret_cast<uint2*>(g_xh + xbase + a * DIM) = raw;

            // Combine halves on packed values, add into this warp's slice
            // (half==0 lanes write distinct float4 slots -- race-free).
            const u64 olo = __shfl_down_sync(0xffffffffu, xlo, 16);
            const u64 ohi = __shfl_down_sync(0xffffffffu, xhi, 16);
            xlo = add2(xlo, olo);
            xhi = add2(xhi, ohi);
            if (half == 0) {
                const float2 a01 = u2f(xlo);
                const float2 a23 = u2f(xhi);
                float4* slot = reinterpret_cast<float4*>(myslice + a * 64 + 4 * lh);
                float4 cur = *slot;
                cur.x += a01.x; cur.y += a01.y;
                cur.z += a23.x; cur.w += a23.y;
                *slot = cur;
            }
        }
    }

    __syncthreads();
    // Reduce the 4 warp slices in double, one global double atomic per element.
    for (int i = tid; i < G * 64; i += 128) {
        double tot = 0.0;
        #pragma unroll
        for (int ws = 0; ws < 4; ws++) tot += (double)sblk[ws * (G * 64) + i];
        atomicAdd(&g_sums[SUMBASE + b * (G * 64) + i], tot);
    }
}

// Fused pass 1 (128 threads/block, 32 positions/block), LPT ordering:
// heavier G=6 blocks first -> blocks [0,1024): g0, [1024,1536): g1,
// [1536,1792): g2 (g0 already first; kept -- lighter g2 blocks land last).
__global__ void __launch_bounds__(128) pass1_fused_kernel(
    const float* __restrict__ q,
    const float* __restrict__ k,
    const float* __restrict__ v)
{
    grid_dep_wait();   // PDL: gate before any memory op
    __shared__ float sblk[4 * 6 * 64];   // 6 KB: per-warp sum slices
    const int bx = blockIdx.x;
    if (bx < 1024) {
        pass1_body<6, 1, 0, 0, 8192, X0_BASE, S0_BASE>(bx, sblk, q, k, v);
    } else if (bx < 1536) {
        pass1_body<5, 2, 1, 5, 4096, X1_BASE, S1_BASE>(bx - 1024, sblk, q, k, v);
    } else {
        pass1_body<5, 4, 2, 10, 2048, X2_BASE, S2_BASE>(bx - 1536, sblk, q, k, v);
    }
}

__device__ __forceinline__ float4 xload(int xoff, float4 rv)
{
    const uint2 raw = *reinterpret_cast<const uint2*>(g_xh + xoff);
    const __half2 h01 = *reinterpret_cast<const __half2*>(&raw.x);
    const __half2 h23 = *reinterpret_cast<const __half2*>(&raw.y);
    const float2 f01 = __half22float2(h01);
    const float2 f23 = __half22float2(h23);
    return make_float4(f01.x * rv.x, f01.y * rv.y, f23.x * rv.z, f23.y * rv.w);
}

// Streaming 16B store (output: written once, never read -> keep L2 for x).
__device__ __forceinline__ void stcs4(float4* p, float4 val) {
    asm volatile("st.global.cs.v4.f32 [%0], {%1, %2, %3, %4};"
                 :: "l"(p), "f"(val.x), "f"(val.y), "f"(val.z), "f"(val.w)
                 : "memory");
}

// Pass 2: each thread writes EIGHT float4s at positions ph + i*1024, i=0..7
// (stride 1024 preserves parity -> identical group predicates, shared rsums,
// 8-deep load MLP). t layout: d4 (16) | h (16) | ph (1024) | b (4).
// Also re-zeroes g_sums (already consumed by rsums_kernel) for next launch.
__global__ void __launch_bounds__(256) pass2_kernel(float* __restrict__ out)
{
    grid_dep_wait();   // rsums_kernel must have finished reading g_sums

    const int t = blockIdx.x * 256 + threadIdx.x;
    if (t < S_TOTAL) g_sums[t] = 0.0;

    const int d4 = t & 15;
    const int h  = (t >> 4) & 15;
    const int ph = (t >> 8) & 1023;     // p_i = ph + i*1024, i in 0..7
    const int b  = t >> 18;

    float4 vo[8];
    #pragma unroll
    for (int i = 0; i < 8; i++) vo[i] = make_float4(0.f, 0.f, 0.f, 0.f);

    const int e = (d4 << 2);

    if (h < 6) { // group 0: all positions
        const float4 rv = *reinterpret_cast<const float4*>(
            g_rsums + S0_BASE + (((b * 6 + h) << 6) + e));
        const int j0 = b * 8192 + ph;           // j stride per output = 1024
        #pragma unroll
        for (int i = 0; i < 8; i++)
            vo[i] = xload(X0_BASE + (((j0 + i * 1024) * 6 + h) << 6) + e, rv);
    }
    if (h >= 5 && h < 10 && (ph & 1) == 1) { // group 1: odd positions
        const int hh = h - 5;
        const float4 rv = *reinterpret_cast<const float4*>(
            g_rsums + S1_BASE + (((b * 5 + hh) << 6) + e));
        const int j0 = b * 4096 + (ph >> 1);    // j stride per output = 512
        #pragma unroll
        for (int i = 0; i < 8; i++) {
            const float4 ti = xload(X1_BASE + (((j0 + i * 512) * 5 + hh) << 6) + e, rv);
            vo[i].x += ti.x; vo[i].y += ti.y; vo[i].z += ti.z; vo[i].w += ti.w;
        }
    }
    if (h >= 10 && h < 15 && (ph & 3) == 2) { // group 2: pos%4==2
        const int hh = h - 10;
        const float4 rv = *reinterpret_cast<const float4*>(
            g_rsums + S2_BASE + (((b * 5 + hh) << 6) + e));
        const int j0 = b * 2048 + (ph >> 2);    // j stride per output = 256
        #pragma unroll
        for (int i = 0; i < 8; i++) {
            const float4 ti = xload(X2_BASE + (((j0 + i * 256) * 5 + hh) << 6) + e, rv);
            vo[i].x += ti.x; vo[i].y += ti.y; vo[i].z += ti.z; vo[i].w += ti.w;
        }
    }

    const int o0 = (b * 8192 + ph) * 256 + h * 16 + d4;  // float4 index
    const int ostride = 1024 * 256;
    float4* o = reinterpret_cast<float4*>(out);
    #pragma unroll
    for (int i = 0; i < 8; i++)
        stcs4(o + o0 + i * ostride, vo[i]);
}

// Launch with Programmatic Stream Serialization: launch latency overlaps the
// preceding kernel's tail; ordering enforced by griddepcontrol.wait inside.
template <typename... Args>
static inline void launch_pdl(void (*fn)(Args...), dim3 grid, dim3 block,
                              Args... args)
{
    cudaLaunchConfig_t cfg = {};
    cfg.gridDim  = grid;
    cfg.blockDim = block;
    cfg.dynamicSmemBytes = 0;
    cfg.stream   = 0;
    cudaLaunchAttribute attr[1];
    attr[0].id = cudaLaunchAttributeProgrammaticStreamSerialization;
    attr[0].val.programmaticStreamSerializationAllowed = 1;
    cfg.attrs    = attr;
    cfg.numAttrs = 1;
    cudaLaunchKernelEx(&cfg, fn, args...);
}

extern "C" void kernel_launch(void* const* d_in, const int* in_sizes, int n_in,
                              void* d_out, int out_size)
{
    const float* q = (const float*)d_in[0];
    const float* k = (const float*)d_in[1];
    const float* v = (const float*)d_in[2];
    float* out = (float*)d_out;

    // Pass 1: 1024 (g0) + 512 (g1) + 256 (g2) blocks, 32 positions each.
    // g_sums starts zeroed (static init; re-zeroed by pass2 each launch).
    launch_pdl(pass1_fused_kernel, dim3(1792), dim3(128), q, k, v);

    // rsums + pass2 ride PDL.
    launch_pdl(rsums_kernel, dim3(16), dim3(256));
    launch_pdl(pass2_kernel, dim3(4096), dim3(256), out);
}